// round 16
// baseline (speedup 1.0000x reference)
#include <cuda_runtime.h>
#include <cstdint>

// ---------------- problem constants ----------------
static constexpr int H   = 128;
static constexpr int NUc = 200000;
static constexpr int NMc = 80000;
static constexpr int FDc = 512;

// ---------------- scratch (device globals; no allocation allowed) ----------------
__device__ __align__(128) float g_mx   [(size_t)NMc * H];  // movie_x, later movie_o
__device__ __align__(128) float g_t1   [(size_t)NMc * H];  // movie_x @ Wl1_mu
__device__ __align__(128) float g_mh   [(size_t)NMc * H];  // movie_h
__device__ __align__(128) float g_t2   [(size_t)NMc * H];  // movie_h @ Wl2_mu
__device__ __align__(128) float g_aggM [(size_t)NMc * H];
__device__ __align__(128) float g_aggU1[(size_t)NUc * H];  // conv1 user agg (raw sums)
__device__ __align__(128) float g_aggU2[(size_t)NUc * H];  // conv2 user agg, later user_o
__device__ __align__(128) int   g_deg_u[NUc];
__device__ __align__(128) int   g_deg_m[NMc];
__device__ __align__(128) float g_u1 [H];   // user_init @ Wl1_um
__device__ __align__(128) float g_cU1[H];   // bl1_mu + user_init @ Wr1_mu

// ---------------- utility kernels ----------------
__global__ void zero_f4(float* __restrict__ p, int n4) {
    int i = blockIdx.x * blockDim.x + threadIdx.x;
    if (i < n4) reinterpret_cast<float4*>(p)[i] = make_float4(0.f, 0.f, 0.f, 0.f);
}

__global__ void zero_int(int* __restrict__ p, int n) {
    int i = blockIdx.x * blockDim.x + threadIdx.x;
    if (i < n) p[i] = 0;
}

__global__ void degrees_kernel(const int* __restrict__ es, const int* __restrict__ ed,
                               int* __restrict__ deg_u, int* __restrict__ deg_m, int E) {
    int i = blockIdx.x * blockDim.x + threadIdx.x;
    if (i < E) {
        atomicAdd(&deg_u[es[i]], 1);
        atomicAdd(&deg_m[ed[i]], 1);
    }
}

// u1 = user_init @ Wl1_um ; cU1 = bl1_mu + user_init @ Wr1_mu
__global__ void precompute_kernel(const float* __restrict__ uinit,
                                  const float* __restrict__ Wl1_um,
                                  const float* __restrict__ bl1_mu,
                                  const float* __restrict__ Wr1_mu) {
    int j = threadIdx.x;  // 0..127
    float s1 = 0.f, s2 = 0.f;
    for (int i = 0; i < H; i++) {
        float u = uinit[i];
        s1 = fmaf(u, Wl1_um[i * H + j], s1);
        s2 = fmaf(u, Wr1_mu[i * H + j], s2);
    }
    g_u1[j]  = s1;
    g_cU1[j] = bl1_mu[j] + s2;
}

// ---------------- tf32 helpers ----------------
__device__ __forceinline__ uint32_t f2tf32(float f) {
    uint32_t o;
    asm("cvt.rna.tf32.f32 %0, %1;" : "=r"(o) : "f"(f));
    return o;
}

__device__ __forceinline__ void mma_tf32(float c[4], const uint32_t a[4], const uint32_t b[2]) {
    asm volatile(
        "mma.sync.aligned.m16n8k8.row.col.f32.tf32.tf32.f32 "
        "{%0,%1,%2,%3}, {%4,%5,%6,%7}, {%8,%9}, {%0,%1,%2,%3};"
        : "+f"(c[0]), "+f"(c[1]), "+f"(c[2]), "+f"(c[3])
        : "r"(a[0]), "r"(a[1]), "r"(a[2]), "r"(a[3]), "r"(b[0]), "r"(b[1]));
}

// ---------------- tensor-core GEMM: C[M,128] = f(A)[M,K] @ W[K,128] (+epilogue) ----------------
// A-side transform (if adeg != nullptr): a = relu(a * 1/max(adeg[row],1) + acvec[col])
//   (used to consume user_h virtually from raw aggregate sums)
// Epilogue modes:
//   0: C = acc + bias(optional)
//   1: C = relu(acc + bias + (deg[row]>0 ? u1 : 0))
//   2: C = acc + bias + C_prev * (1/max(deg[row],1))
//   3: C = acc * (1/max(deg[row],1)) + bias
//   4: C = C_prev + acc
__global__ __launch_bounds__(256) void gemm_tc(
    const float* __restrict__ A, const float* __restrict__ W,
    float* __restrict__ C, int M, int K,
    const float* __restrict__ bias,
    const float* __restrict__ u1,
    const int* __restrict__ deg,
    int mode,
    const int* __restrict__ adeg,
    const float* __restrict__ acvec)
{
    // A tile: [128 rows][32 k], row stride 36 -> bank (4m+k)%32 conflict-free frag loads
    __shared__ uint32_t As[128 * 36];
    // W tile: [32 k][128 n], row stride 136 -> bank (8k+n)%32 conflict-free frag loads
    __shared__ uint32_t Ws[32 * 136];

    const int tid   = threadIdx.x;
    const int lane  = tid & 31;
    const int wid   = tid >> 5;
    const int warpM = wid >> 1;          // 0..3
    const int warpN = wid & 1;           // 0..1
    const int row0  = blockIdx.x * 128;

    float acc[2][8][4];
#pragma unroll
    for (int mb = 0; mb < 2; mb++)
#pragma unroll
        for (int nb = 0; nb < 8; nb++) {
            acc[mb][nb][0] = 0.f; acc[mb][nb][1] = 0.f;
            acc[mb][nb][2] = 0.f; acc[mb][nb][3] = 0.f;
        }

    for (int k0 = 0; k0 < K; k0 += 32) {
        // ---- load A tile (128x32 fp32 = 1024 float4 over 256 threads) ----
#pragma unroll
        for (int l = 0; l < 4; l++) {
            int idx  = tid + l * 256;
            int r    = idx >> 3;          // 0..127
            int c4   = idx & 7;           // float4 within the 32-wide row
            int grow = row0 + r;
            float4 v = make_float4(0.f, 0.f, 0.f, 0.f);
            if (grow < M) {
                v = *reinterpret_cast<const float4*>(A + (size_t)grow * K + k0 + c4 * 4);
                if (adeg) {
                    float inv = 1.f / (float)max(adeg[grow], 1);
                    float4 cc = *reinterpret_cast<const float4*>(acvec + k0 + c4 * 4);
                    v.x = fmaxf(fmaf(v.x, inv, cc.x), 0.f);
                    v.y = fmaxf(fmaf(v.y, inv, cc.y), 0.f);
                    v.z = fmaxf(fmaf(v.z, inv, cc.z), 0.f);
                    v.w = fmaxf(fmaf(v.w, inv, cc.w), 0.f);
                }
            }
            uint4 t;
            t.x = f2tf32(v.x); t.y = f2tf32(v.y); t.z = f2tf32(v.z); t.w = f2tf32(v.w);
            *reinterpret_cast<uint4*>(&As[r * 36 + c4 * 4]) = t;
        }
        // ---- load W tile (32x128 fp32 = 1024 float4 over 256 threads) ----
#pragma unroll
        for (int l = 0; l < 4; l++) {
            int idx = tid + l * 256;
            int r   = idx >> 5;           // 0..31
            int c   = idx & 31;           // float4 within the 128-wide row
            float4 v = *reinterpret_cast<const float4*>(W + (size_t)(k0 + r) * H + c * 4);
            uint4 t;
            t.x = f2tf32(v.x); t.y = f2tf32(v.y); t.z = f2tf32(v.z); t.w = f2tf32(v.w);
            *reinterpret_cast<uint4*>(&Ws[r * 136 + c * 4]) = t;
        }
        __syncthreads();

#pragma unroll
        for (int s = 0; s < 4; s++) {
            const int ka = s * 8 + (lane & 3);
            uint32_t a[2][4];
#pragma unroll
            for (int mb = 0; mb < 2; mb++) {
                int mA = warpM * 32 + mb * 16 + (lane >> 2);
                a[mb][0] = As[mA * 36 + ka];
                a[mb][1] = As[(mA + 8) * 36 + ka];
                a[mb][2] = As[mA * 36 + ka + 4];
                a[mb][3] = As[(mA + 8) * 36 + ka + 4];
            }
            uint32_t b[8][2];
            const int nB = warpN * 64 + (lane >> 2);
#pragma unroll
            for (int nb = 0; nb < 8; nb++) {
                b[nb][0] = Ws[ka * 136 + nB + nb * 8];
                b[nb][1] = Ws[(ka + 4) * 136 + nB + nb * 8];
            }
#pragma unroll
            for (int mb = 0; mb < 2; mb++)
#pragma unroll
                for (int nb = 0; nb < 8; nb++)
                    mma_tf32(acc[mb][nb], a[mb], b[nb]);
        }
        __syncthreads();
    }

    // ---------------- epilogue ----------------
    const int col0 = warpN * 64 + (lane & 3) * 2;

#pragma unroll
    for (int mb = 0; mb < 2; mb++) {
        int rA = row0 + warpM * 32 + mb * 16 + (lane >> 2);
        int rB = rA + 8;
        float invA = 1.f, invB = 1.f;
        int   dA = 0,    dB = 0;
        if (deg) {
            if (rA < M) { dA = deg[rA]; invA = 1.f / (float)max(dA, 1); }
            if (rB < M) { dB = deg[rB]; invB = 1.f / (float)max(dB, 1); }
        }
#pragma unroll
        for (int nb = 0; nb < 8; nb++) {
            int n = col0 + nb * 8;
            float bx = 0.f, by = 0.f;
            if (bias) { bx = bias[n]; by = bias[n + 1]; }
            float c0 = acc[mb][nb][0], c1 = acc[mb][nb][1];
            float c2 = acc[mb][nb][2], c3 = acc[mb][nb][3];

            if (rA < M) {
                float* cp = C + (size_t)rA * H + n;
                float ox, oy;
                if (mode == 0) {
                    ox = c0 + bx; oy = c1 + by;
                } else if (mode == 1) {
                    ox = c0 + bx; oy = c1 + by;
                    if (dA > 0) { ox += u1[n]; oy += u1[n + 1]; }
                    ox = fmaxf(ox, 0.f); oy = fmaxf(oy, 0.f);
                } else if (mode == 2) {
                    float2 p = *reinterpret_cast<const float2*>(cp);
                    ox = c0 + bx + p.x * invA; oy = c1 + by + p.y * invA;
                } else if (mode == 3) {
                    ox = c0 * invA + bx; oy = c1 * invA + by;
                } else { // mode 4
                    float2 p = *reinterpret_cast<const float2*>(cp);
                    ox = p.x + c0; oy = p.y + c1;
                }
                *reinterpret_cast<float2*>(cp) = make_float2(ox, oy);
            }
            if (rB < M) {
                float* cp = C + (size_t)rB * H + n;
                float ox, oy;
                if (mode == 0) {
                    ox = c2 + bx; oy = c3 + by;
                } else if (mode == 1) {
                    ox = c2 + bx; oy = c3 + by;
                    if (dB > 0) { ox += u1[n]; oy += u1[n + 1]; }
                    ox = fmaxf(ox, 0.f); oy = fmaxf(oy, 0.f);
                } else if (mode == 2) {
                    float2 p = *reinterpret_cast<const float2*>(cp);
                    ox = c2 + bx + p.x * invB; oy = c3 + by + p.y * invB;
                } else if (mode == 3) {
                    ox = c2 * invB + bx; oy = c3 * invB + by;
                } else { // mode 4
                    float2 p = *reinterpret_cast<const float2*>(cp);
                    ox = p.x + c2; oy = p.y + c3;
                }
                *reinterpret_cast<float2*>(cp) = make_float2(ox, oy);
            }
        }
    }
}

// ---------------- atomics ----------------
__device__ __forceinline__ void atomic_add_f4(float4* addr, float4 v) {
#if __CUDA_ARCH__ >= 900
    atomicAdd(addr, v);
#else
    float* f = reinterpret_cast<float*>(addr);
    atomicAdd(f + 0, v.x); atomicAdd(f + 1, v.y);
    atomicAdd(f + 2, v.z); atomicAdd(f + 3, v.w);
#endif
}

// ---------------- fused user-side scatter: a1[src] += t1[dst]; a2[src] += t2[dst] ----------------
__global__ __launch_bounds__(256) void scatter_user2(
    const float* __restrict__ t1, const float* __restrict__ t2,
    const int* __restrict__ esrc, const int* __restrict__ edst,
    float* __restrict__ a1, float* __restrict__ a2, int E)
{
    int w = (blockIdx.x * blockDim.x + threadIdx.x) >> 5;
    int lane = threadIdx.x & 31;
    if (w >= E) return;
    int g = edst[w];   // movie (gather)
    int s = esrc[w];   // user  (scatter)
    size_t go = (size_t)g * H + lane * 4;
    size_t so = (size_t)s * H + lane * 4;
    float4 v1 = *reinterpret_cast<const float4*>(t1 + go);
    float4 v2 = *reinterpret_cast<const float4*>(t2 + go);
    atomic_add_f4(reinterpret_cast<float4*>(a1 + so), v1);
    atomic_add_f4(reinterpret_cast<float4*>(a2 + so), v2);
}

// ---------------- movie-side scatter with virtual user_h ----------------
// aggM[dst] += relu(aggU1[src]/max(deg_u[src],1) + cU1)
__global__ __launch_bounds__(256) void scatter_movie_uh(
    const float* __restrict__ aggU1,
    const int* __restrict__ esrc, const int* __restrict__ edst,
    const int* __restrict__ deg_u,
    float* __restrict__ aggM, int E)
{
    int w = (blockIdx.x * blockDim.x + threadIdx.x) >> 5;
    int lane = threadIdx.x & 31;
    if (w >= E) return;
    int g = esrc[w];   // user (gather)
    int s = edst[w];   // movie (scatter)
    float inv = 1.f / (float)max(deg_u[g], 1);
    float4 v = *reinterpret_cast<const float4*>(aggU1 + (size_t)g * H + lane * 4);
    float4 c = *reinterpret_cast<const float4*>(g_cU1 + lane * 4);
    v.x = fmaxf(fmaf(v.x, inv, c.x), 0.f);
    v.y = fmaxf(fmaf(v.y, inv, c.y), 0.f);
    v.z = fmaxf(fmaf(v.z, inv, c.z), 0.f);
    v.w = fmaxf(fmaf(v.w, inv, c.w), 0.f);
    atomic_add_f4(reinterpret_cast<float4*>(aggM + (size_t)s * H + lane * 4), v);
}

// ---------------- out[e] = dot(user_o[lu[e]], movie_o[lm[e]]) ----------------
__global__ __launch_bounds__(256) void edge_dot(
    const float* __restrict__ uo, const float* __restrict__ mo,
    const int* __restrict__ lu, const int* __restrict__ lm,
    float* __restrict__ out, int EL)
{
    int w = (blockIdx.x * blockDim.x + threadIdx.x) >> 5;
    int lane = threadIdx.x & 31;
    if (w >= EL) return;
    float4 a = *reinterpret_cast<const float4*>(uo + (size_t)lu[w] * H + lane * 4);
    float4 b = *reinterpret_cast<const float4*>(mo + (size_t)lm[w] * H + lane * 4);
    float d = a.x * b.x + a.y * b.y + a.z * b.z + a.w * b.w;
#pragma unroll
    for (int off = 16; off; off >>= 1) d += __shfl_xor_sync(0xffffffffu, d, off);
    if (lane == 0) out[w] = d;
}

// ---------------- launcher ----------------
extern "C" void kernel_launch(void* const* d_in, const int* in_sizes, int n_in,
                              void* d_out, int out_size)
{
    const float* movie_feats = (const float*)d_in[0];
    const float* user_init   = (const float*)d_in[1];
    const int*   edge_src    = (const int*)d_in[2];
    const int*   edge_dst    = (const int*)d_in[3];
    const int*   lbl_user    = (const int*)d_in[4];
    const int*   lbl_movie   = (const int*)d_in[5];
    const int base = (n_in >= 21) ? 7 : 6;
    const float* Wm     = (const float*)d_in[base + 0];
    const float* bm     = (const float*)d_in[base + 1];
    const float* Wl1_um = (const float*)d_in[base + 2];
    const float* bl1_um = (const float*)d_in[base + 3];
    const float* Wr1_um = (const float*)d_in[base + 4];
    const float* Wl1_mu = (const float*)d_in[base + 5];
    const float* bl1_mu = (const float*)d_in[base + 6];
    const float* Wr1_mu = (const float*)d_in[base + 7];
    const float* Wl2_um = (const float*)d_in[base + 8];
    const float* bl2_um = (const float*)d_in[base + 9];
    const float* Wr2_um = (const float*)d_in[base + 10];
    const float* Wl2_mu = (const float*)d_in[base + 11];
    const float* bl2_mu = (const float*)d_in[base + 12];
    const float* Wr2_mu = (const float*)d_in[base + 13];

    const int E  = in_sizes[2];
    const int EL = in_sizes[4];
    const int nm = in_sizes[0] / FDc;   // 80000
    const int nu = NUc;                 // 200000

    void *p_mx, *p_t1, *p_mh, *p_t2, *p_aM, *p_a1, *p_a2, *p_du, *p_dm, *p_u1, *p_c1;
    cudaGetSymbolAddress(&p_mx, g_mx);
    cudaGetSymbolAddress(&p_t1, g_t1);
    cudaGetSymbolAddress(&p_mh, g_mh);
    cudaGetSymbolAddress(&p_t2, g_t2);
    cudaGetSymbolAddress(&p_aM, g_aggM);
    cudaGetSymbolAddress(&p_a1, g_aggU1);
    cudaGetSymbolAddress(&p_a2, g_aggU2);
    cudaGetSymbolAddress(&p_du, g_deg_u);
    cudaGetSymbolAddress(&p_dm, g_deg_m);
    cudaGetSymbolAddress(&p_u1, g_u1);
    cudaGetSymbolAddress(&p_c1, g_cU1);

    float* mx = (float*)p_mx;   float* t1 = (float*)p_t1;
    float* mh = (float*)p_mh;   float* t2 = (float*)p_t2;
    float* aM = (float*)p_aM;
    float* a1 = (float*)p_a1;   float* a2 = (float*)p_a2;
    int* du = (int*)p_du;       int* dm = (int*)p_dm;
    float* u1 = (float*)p_u1;   float* cU1 = (float*)p_c1;
    float* out = (float*)d_out;

    const int TB = 256;
    const int nu4 = nu * 32, nm4 = nm * 32;
    const int gNM = (nm + 127) / 128;
    const int gNU = (nu + 127) / 128;

    // 0-2: degree prep + constants
    zero_int<<<(nu + TB - 1) / TB, TB>>>(du, nu);
    zero_int<<<(nm + TB - 1) / TB, TB>>>(dm, nm);
    precompute_kernel<<<1, H>>>(user_init, Wl1_um, bl1_mu, Wr1_mu);

    // 3: movie_x = movie_feats @ Wm + bm   (big K=512 GEMM — placed here for ncu sampling)
    gemm_tc<<<gNM, TB>>>(movie_feats, Wm, mx, nm, FDc, bm, nullptr, nullptr, 0, nullptr, nullptr);

    // 4: degrees
    degrees_kernel<<<(E + TB - 1) / TB, TB>>>(edge_src, edge_dst, du, dm, E);

    // 5: t1 = movie_x @ Wl1_mu
    gemm_tc<<<gNM, TB>>>(mx, Wl1_mu, t1, nm, H, nullptr, nullptr, nullptr, 0, nullptr, nullptr);
    // 6: movie_h = relu(movie_x @ Wr1_um + bl1_um + (deg_m>0)*u1)
    gemm_tc<<<gNM, TB>>>(mx, Wr1_um, mh, nm, H, bl1_um, u1, dm, 1, nullptr, nullptr);
    // 7: t2 = movie_h @ Wl2_mu
    gemm_tc<<<gNM, TB>>>(mh, Wl2_mu, t2, nm, H, nullptr, nullptr, nullptr, 0, nullptr, nullptr);

    // 8-9: zero user accumulators
    zero_f4<<<(nu4 + TB - 1) / TB, TB>>>(a1, nu4);
    zero_f4<<<(nu4 + TB - 1) / TB, TB>>>(a2, nu4);

    // 10: fused user-side scatter (t1 -> aggU1, t2 -> aggU2)
    scatter_user2<<<(E + 7) / 8, TB>>>(t1, t2, edge_src, edge_dst, a1, a2, E);

    // 11: zero movie accumulator
    zero_f4<<<(nm4 + TB - 1) / TB, TB>>>(aM, nm4);

    // 12: movie-side scatter of virtual user_h = relu(aggU1/deg + cU1)
    scatter_movie_uh<<<(E + 7) / 8, TB>>>(a1, edge_src, edge_dst, du, aM, E);

    // 13: user_o (in place over aggU2) = user_h @ Wr2_mu + bl2_mu + aggU2/deg
    //     user_h consumed virtually from aggU1 via A-side transform
    gemm_tc<<<gNU, TB>>>(a1, Wr2_mu, a2, nu, H, bl2_mu, nullptr, du, 2, du, cU1);

    // 14: movie_o (into g_mx) = (aggM/deg_m) @ Wl2_um + bl2_um ...
    gemm_tc<<<gNM, TB>>>(aM, Wl2_um, mx, nm, H, bl2_um, nullptr, dm, 3, nullptr, nullptr);
    // 15: ... += movie_h @ Wr2_um
    gemm_tc<<<gNM, TB>>>(mh, Wr2_um, mx, nm, H, nullptr, nullptr, nullptr, 4, nullptr, nullptr);

    // 16: supervision-edge dot products
    edge_dot<<<(EL + 7) / 8, TB>>>(a2, mx, lbl_user, lbl_movie, out, EL);
}

// round 17
// speedup vs baseline: 1.0004x; 1.0004x over previous
#include <cuda_runtime.h>
#include <cstdint>

// ---------------- problem constants ----------------
static constexpr int H   = 128;
static constexpr int NUc = 200000;
static constexpr int NMc = 80000;
static constexpr int FDc = 512;

// ---------------- scratch (device globals; no allocation allowed) ----------------
__device__ __align__(128) float g_mx   [(size_t)NMc * H];  // movie_x, later movie_o
__device__ __align__(128) float g_t1   [(size_t)NMc * H];  // movie_x @ Wl1_mu
__device__ __align__(128) float g_mh   [(size_t)NMc * H];  // movie_h
__device__ __align__(128) float g_t2   [(size_t)NMc * H];  // movie_h @ Wl2_mu
__device__ __align__(128) float g_aggM [(size_t)NMc * H];
__device__ __align__(128) float g_aggU1[(size_t)NUc * H];  // conv1 user agg (raw sums)
__device__ __align__(128) float g_aggU2[(size_t)NUc * H];  // conv2 user agg, later user_o
__device__ __align__(128) int   g_deg_u[NUc];
__device__ __align__(128) int   g_deg_m[NMc];
__device__ __align__(128) float g_u1 [H];   // user_init @ Wl1_um
__device__ __align__(128) float g_cU1[H];   // bl1_mu + user_init @ Wr1_mu

// ---------------- utility kernels ----------------
__global__ void zero_f4(float* __restrict__ p, int n4) {
    int i = blockIdx.x * blockDim.x + threadIdx.x;
    if (i < n4) reinterpret_cast<float4*>(p)[i] = make_float4(0.f, 0.f, 0.f, 0.f);
}

__global__ void zero_int(int* __restrict__ p, int n) {
    int i = blockIdx.x * blockDim.x + threadIdx.x;
    if (i < n) p[i] = 0;
}

__global__ void degrees_kernel(const int* __restrict__ es, const int* __restrict__ ed,
                               int* __restrict__ deg_u, int* __restrict__ deg_m, int E) {
    int i = blockIdx.x * blockDim.x + threadIdx.x;
    if (i < E) {
        atomicAdd(&deg_u[es[i]], 1);
        atomicAdd(&deg_m[ed[i]], 1);
    }
}

// u1 = user_init @ Wl1_um ; cU1 = bl1_mu + user_init @ Wr1_mu
__global__ void precompute_kernel(const float* __restrict__ uinit,
                                  const float* __restrict__ Wl1_um,
                                  const float* __restrict__ bl1_mu,
                                  const float* __restrict__ Wr1_mu) {
    int j = threadIdx.x;  // 0..127
    float s1 = 0.f, s2 = 0.f;
    for (int i = 0; i < H; i++) {
        float u = uinit[i];
        s1 = fmaf(u, Wl1_um[i * H + j], s1);
        s2 = fmaf(u, Wr1_mu[i * H + j], s2);
    }
    g_u1[j]  = s1;
    g_cU1[j] = bl1_mu[j] + s2;
}

// ---------------- tf32 helpers ----------------
__device__ __forceinline__ uint32_t f2tf32(float f) {
    uint32_t o;
    asm("cvt.rna.tf32.f32 %0, %1;" : "=r"(o) : "f"(f));
    return o;
}

__device__ __forceinline__ void mma_tf32(float c[4], const uint32_t a[4], const uint32_t b[2]) {
    asm volatile(
        "mma.sync.aligned.m16n8k8.row.col.f32.tf32.tf32.f32 "
        "{%0,%1,%2,%3}, {%4,%5,%6,%7}, {%8,%9}, {%0,%1,%2,%3};"
        : "+f"(c[0]), "+f"(c[1]), "+f"(c[2]), "+f"(c[3])
        : "r"(a[0]), "r"(a[1]), "r"(a[2]), "r"(a[3]), "r"(b[0]), "r"(b[1]));
}

// ---------------- tensor-core GEMM: C[M,128] = f(A)[M,K] @ W[K,128] (+epilogue) ----------------
// A-side transform (if adeg != nullptr): a = relu(a * 1/max(adeg[row],1) + acvec[col])
//   (used to consume user_h virtually from raw aggregate sums)
// Epilogue modes:
//   0: C = acc + bias(optional)
//   1: C = relu(acc + bias + (deg[row]>0 ? u1 : 0))
//   2: C = acc + bias + C_prev * (1/max(deg[row],1))
//   3: C = acc * (1/max(deg[row],1)) + bias
//   4: C = C_prev + acc
__global__ __launch_bounds__(256) void gemm_tc(
    const float* __restrict__ A, const float* __restrict__ W,
    float* __restrict__ C, int M, int K,
    const float* __restrict__ bias,
    const float* __restrict__ u1,
    const int* __restrict__ deg,
    int mode,
    const int* __restrict__ adeg,
    const float* __restrict__ acvec)
{
    // A tile: [128 rows][32 k], row stride 36 -> bank (4m+k)%32 conflict-free frag loads
    __shared__ uint32_t As[128 * 36];
    // W tile: [32 k][128 n], row stride 136 -> bank (8k+n)%32 conflict-free frag loads
    __shared__ uint32_t Ws[32 * 136];

    const int tid   = threadIdx.x;
    const int lane  = tid & 31;
    const int wid   = tid >> 5;
    const int warpM = wid >> 1;          // 0..3
    const int warpN = wid & 1;           // 0..1
    const int row0  = blockIdx.x * 128;

    float acc[2][8][4];
#pragma unroll
    for (int mb = 0; mb < 2; mb++)
#pragma unroll
        for (int nb = 0; nb < 8; nb++) {
            acc[mb][nb][0] = 0.f; acc[mb][nb][1] = 0.f;
            acc[mb][nb][2] = 0.f; acc[mb][nb][3] = 0.f;
        }

    for (int k0 = 0; k0 < K; k0 += 32) {
        // ---- load A tile (128x32 fp32 = 1024 float4 over 256 threads) ----
#pragma unroll
        for (int l = 0; l < 4; l++) {
            int idx  = tid + l * 256;
            int r    = idx >> 3;          // 0..127
            int c4   = idx & 7;           // float4 within the 32-wide row
            int grow = row0 + r;
            float4 v = make_float4(0.f, 0.f, 0.f, 0.f);
            if (grow < M) {
                v = *reinterpret_cast<const float4*>(A + (size_t)grow * K + k0 + c4 * 4);
                if (adeg) {
                    float inv = 1.f / (float)max(adeg[grow], 1);
                    float4 cc = *reinterpret_cast<const float4*>(acvec + k0 + c4 * 4);
                    v.x = fmaxf(fmaf(v.x, inv, cc.x), 0.f);
                    v.y = fmaxf(fmaf(v.y, inv, cc.y), 0.f);
                    v.z = fmaxf(fmaf(v.z, inv, cc.z), 0.f);
                    v.w = fmaxf(fmaf(v.w, inv, cc.w), 0.f);
                }
            }
            uint4 t;
            t.x = f2tf32(v.x); t.y = f2tf32(v.y); t.z = f2tf32(v.z); t.w = f2tf32(v.w);
            *reinterpret_cast<uint4*>(&As[r * 36 + c4 * 4]) = t;
        }
        // ---- load W tile (32x128 fp32 = 1024 float4 over 256 threads) ----
#pragma unroll
        for (int l = 0; l < 4; l++) {
            int idx = tid + l * 256;
            int r   = idx >> 5;           // 0..31
            int c   = idx & 31;           // float4 within the 128-wide row
            float4 v = *reinterpret_cast<const float4*>(W + (size_t)(k0 + r) * H + c * 4);
            uint4 t;
            t.x = f2tf32(v.x); t.y = f2tf32(v.y); t.z = f2tf32(v.z); t.w = f2tf32(v.w);
            *reinterpret_cast<uint4*>(&Ws[r * 136 + c * 4]) = t;
        }
        __syncthreads();

#pragma unroll
        for (int s = 0; s < 4; s++) {
            const int ka = s * 8 + (lane & 3);
            uint32_t a[2][4];
#pragma unroll
            for (int mb = 0; mb < 2; mb++) {
                int mA = warpM * 32 + mb * 16 + (lane >> 2);
                a[mb][0] = As[mA * 36 + ka];
                a[mb][1] = As[(mA + 8) * 36 + ka];
                a[mb][2] = As[mA * 36 + ka + 4];
                a[mb][3] = As[(mA + 8) * 36 + ka + 4];
            }
            uint32_t b[8][2];
            const int nB = warpN * 64 + (lane >> 2);
#pragma unroll
            for (int nb = 0; nb < 8; nb++) {
                b[nb][0] = Ws[ka * 136 + nB + nb * 8];
                b[nb][1] = Ws[(ka + 4) * 136 + nB + nb * 8];
            }
#pragma unroll
            for (int mb = 0; mb < 2; mb++)
#pragma unroll
                for (int nb = 0; nb < 8; nb++)
                    mma_tf32(acc[mb][nb], a[mb], b[nb]);
        }
        __syncthreads();
    }

    // ---------------- epilogue ----------------
    const int col0 = warpN * 64 + (lane & 3) * 2;

#pragma unroll
    for (int mb = 0; mb < 2; mb++) {
        int rA = row0 + warpM * 32 + mb * 16 + (lane >> 2);
        int rB = rA + 8;
        float invA = 1.f, invB = 1.f;
        int   dA = 0,    dB = 0;
        if (deg) {
            if (rA < M) { dA = deg[rA]; invA = 1.f / (float)max(dA, 1); }
            if (rB < M) { dB = deg[rB]; invB = 1.f / (float)max(dB, 1); }
        }
#pragma unroll
        for (int nb = 0; nb < 8; nb++) {
            int n = col0 + nb * 8;
            float bx = 0.f, by = 0.f;
            if (bias) { bx = bias[n]; by = bias[n + 1]; }
            float c0 = acc[mb][nb][0], c1 = acc[mb][nb][1];
            float c2 = acc[mb][nb][2], c3 = acc[mb][nb][3];

            if (rA < M) {
                float* cp = C + (size_t)rA * H + n;
                float ox, oy;
                if (mode == 0) {
                    ox = c0 + bx; oy = c1 + by;
                } else if (mode == 1) {
                    ox = c0 + bx; oy = c1 + by;
                    if (dA > 0) { ox += u1[n]; oy += u1[n + 1]; }
                    ox = fmaxf(ox, 0.f); oy = fmaxf(oy, 0.f);
                } else if (mode == 2) {
                    float2 p = *reinterpret_cast<const float2*>(cp);
                    ox = c0 + bx + p.x * invA; oy = c1 + by + p.y * invA;
                } else if (mode == 3) {
                    ox = c0 * invA + bx; oy = c1 * invA + by;
                } else { // mode 4
                    float2 p = *reinterpret_cast<const float2*>(cp);
                    ox = p.x + c0; oy = p.y + c1;
                }
                *reinterpret_cast<float2*>(cp) = make_float2(ox, oy);
            }
            if (rB < M) {
                float* cp = C + (size_t)rB * H + n;
                float ox, oy;
                if (mode == 0) {
                    ox = c2 + bx; oy = c3 + by;
                } else if (mode == 1) {
                    ox = c2 + bx; oy = c3 + by;
                    if (dB > 0) { ox += u1[n]; oy += u1[n + 1]; }
                    ox = fmaxf(ox, 0.f); oy = fmaxf(oy, 0.f);
                } else if (mode == 2) {
                    float2 p = *reinterpret_cast<const float2*>(cp);
                    ox = c2 + bx + p.x * invB; oy = c3 + by + p.y * invB;
                } else if (mode == 3) {
                    ox = c2 * invB + bx; oy = c3 * invB + by;
                } else { // mode 4
                    float2 p = *reinterpret_cast<const float2*>(cp);
                    ox = p.x + c2; oy = p.y + c3;
                }
                *reinterpret_cast<float2*>(cp) = make_float2(ox, oy);
            }
        }
    }
}

// ---------------- atomics ----------------
__device__ __forceinline__ void atomic_add_f4(float4* addr, float4 v) {
#if __CUDA_ARCH__ >= 900
    atomicAdd(addr, v);
#else
    float* f = reinterpret_cast<float*>(addr);
    atomicAdd(f + 0, v.x); atomicAdd(f + 1, v.y);
    atomicAdd(f + 2, v.z); atomicAdd(f + 3, v.w);
#endif
}

// ---------------- fused user-side scatter: a1[src] += t1[dst]; a2[src] += t2[dst] ----------------
__global__ __launch_bounds__(256) void scatter_user2(
    const float* __restrict__ t1, const float* __restrict__ t2,
    const int* __restrict__ esrc, const int* __restrict__ edst,
    float* __restrict__ a1, float* __restrict__ a2, int E)
{
    int w = (blockIdx.x * blockDim.x + threadIdx.x) >> 5;
    int lane = threadIdx.x & 31;
    if (w >= E) return;
    int g = edst[w];   // movie (gather)
    int s = esrc[w];   // user  (scatter)
    size_t go = (size_t)g * H + lane * 4;
    size_t so = (size_t)s * H + lane * 4;
    float4 v1 = *reinterpret_cast<const float4*>(t1 + go);
    float4 v2 = *reinterpret_cast<const float4*>(t2 + go);
    atomic_add_f4(reinterpret_cast<float4*>(a1 + so), v1);
    atomic_add_f4(reinterpret_cast<float4*>(a2 + so), v2);
}

// ---------------- movie-side scatter with virtual user_h ----------------
// aggM[dst] += relu(aggU1[src]/max(deg_u[src],1) + cU1)
__global__ __launch_bounds__(256) void scatter_movie_uh(
    const float* __restrict__ aggU1,
    const int* __restrict__ esrc, const int* __restrict__ edst,
    const int* __restrict__ deg_u,
    float* __restrict__ aggM, int E)
{
    int w = (blockIdx.x * blockDim.x + threadIdx.x) >> 5;
    int lane = threadIdx.x & 31;
    if (w >= E) return;
    int g = esrc[w];   // user (gather)
    int s = edst[w];   // movie (scatter)
    float inv = 1.f / (float)max(deg_u[g], 1);
    float4 v = *reinterpret_cast<const float4*>(aggU1 + (size_t)g * H + lane * 4);
    float4 c = *reinterpret_cast<const float4*>(g_cU1 + lane * 4);
    v.x = fmaxf(fmaf(v.x, inv, c.x), 0.f);
    v.y = fmaxf(fmaf(v.y, inv, c.y), 0.f);
    v.z = fmaxf(fmaf(v.z, inv, c.z), 0.f);
    v.w = fmaxf(fmaf(v.w, inv, c.w), 0.f);
    atomic_add_f4(reinterpret_cast<float4*>(aggM + (size_t)s * H + lane * 4), v);
}

// ---------------- out[e] = dot(user_o[lu[e]], movie_o[lm[e]]) ----------------
__global__ __launch_bounds__(256) void edge_dot(
    const float* __restrict__ uo, const float* __restrict__ mo,
    const int* __restrict__ lu, const int* __restrict__ lm,
    float* __restrict__ out, int EL)
{
    int w = (blockIdx.x * blockDim.x + threadIdx.x) >> 5;
    int lane = threadIdx.x & 31;
    if (w >= EL) return;
    float4 a = *reinterpret_cast<const float4*>(uo + (size_t)lu[w] * H + lane * 4);
    float4 b = *reinterpret_cast<const float4*>(mo + (size_t)lm[w] * H + lane * 4);
    float d = a.x * b.x + a.y * b.y + a.z * b.z + a.w * b.w;
#pragma unroll
    for (int off = 16; off; off >>= 1) d += __shfl_xor_sync(0xffffffffu, d, off);
    if (lane == 0) out[w] = d;
}

// ---------------- launcher ----------------
extern "C" void kernel_launch(void* const* d_in, const int* in_sizes, int n_in,
                              void* d_out, int out_size)
{
    const float* movie_feats = (const float*)d_in[0];
    const float* user_init   = (const float*)d_in[1];
    const int*   edge_src    = (const int*)d_in[2];
    const int*   edge_dst    = (const int*)d_in[3];
    const int*   lbl_user    = (const int*)d_in[4];
    const int*   lbl_movie   = (const int*)d_in[5];
    const int base = (n_in >= 21) ? 7 : 6;
    const float* Wm     = (const float*)d_in[base + 0];
    const float* bm     = (const float*)d_in[base + 1];
    const float* Wl1_um = (const float*)d_in[base + 2];
    const float* bl1_um = (const float*)d_in[base + 3];
    const float* Wr1_um = (const float*)d_in[base + 4];
    const float* Wl1_mu = (const float*)d_in[base + 5];
    const float* bl1_mu = (const float*)d_in[base + 6];
    const float* Wr1_mu = (const float*)d_in[base + 7];
    const float* Wl2_um = (const float*)d_in[base + 8];
    const float* bl2_um = (const float*)d_in[base + 9];
    const float* Wr2_um = (const float*)d_in[base + 10];
    const float* Wl2_mu = (const float*)d_in[base + 11];
    const float* bl2_mu = (const float*)d_in[base + 12];
    const float* Wr2_mu = (const float*)d_in[base + 13];

    const int E  = in_sizes[2];
    const int EL = in_sizes[4];
    const int nm = in_sizes[0] / FDc;   // 80000
    const int nu = NUc;                 // 200000

    void *p_mx, *p_t1, *p_mh, *p_t2, *p_aM, *p_a1, *p_a2, *p_du, *p_dm, *p_u1, *p_c1;
    cudaGetSymbolAddress(&p_mx, g_mx);
    cudaGetSymbolAddress(&p_t1, g_t1);
    cudaGetSymbolAddress(&p_mh, g_mh);
    cudaGetSymbolAddress(&p_t2, g_t2);
    cudaGetSymbolAddress(&p_aM, g_aggM);
    cudaGetSymbolAddress(&p_a1, g_aggU1);
    cudaGetSymbolAddress(&p_a2, g_aggU2);
    cudaGetSymbolAddress(&p_du, g_deg_u);
    cudaGetSymbolAddress(&p_dm, g_deg_m);
    cudaGetSymbolAddress(&p_u1, g_u1);
    cudaGetSymbolAddress(&p_c1, g_cU1);

    float* mx = (float*)p_mx;   float* t1 = (float*)p_t1;
    float* mh = (float*)p_mh;   float* t2 = (float*)p_t2;
    float* aM = (float*)p_aM;
    float* a1 = (float*)p_a1;   float* a2 = (float*)p_a2;
    int* du = (int*)p_du;       int* dm = (int*)p_dm;
    float* u1 = (float*)p_u1;   float* cU1 = (float*)p_c1;
    float* out = (float*)d_out;

    const int TB = 256;
    const int nu4 = nu * 32, nm4 = nm * 32;
    const int gNM = (nm + 127) / 128;
    const int gNU = (nu + 127) / 128;

    // 0-2: degree prep + constants
    zero_int<<<(nu + TB - 1) / TB, TB>>>(du, nu);
    zero_int<<<(nm + TB - 1) / TB, TB>>>(dm, nm);
    precompute_kernel<<<1, H>>>(user_init, Wl1_um, bl1_mu, Wr1_mu);

    // 3: movie_x = movie_feats @ Wm + bm   (big K=512 GEMM — placed here for ncu sampling)
    gemm_tc<<<gNM, TB>>>(movie_feats, Wm, mx, nm, FDc, bm, nullptr, nullptr, 0, nullptr, nullptr);

    // 4: degrees
    degrees_kernel<<<(E + TB - 1) / TB, TB>>>(edge_src, edge_dst, du, dm, E);

    // 5: t1 = movie_x @ Wl1_mu
    gemm_tc<<<gNM, TB>>>(mx, Wl1_mu, t1, nm, H, nullptr, nullptr, nullptr, 0, nullptr, nullptr);
    // 6: movie_h = relu(movie_x @ Wr1_um + bl1_um + (deg_m>0)*u1)
    gemm_tc<<<gNM, TB>>>(mx, Wr1_um, mh, nm, H, bl1_um, u1, dm, 1, nullptr, nullptr);
    // 7: t2 = movie_h @ Wl2_mu
    gemm_tc<<<gNM, TB>>>(mh, Wl2_mu, t2, nm, H, nullptr, nullptr, nullptr, 0, nullptr, nullptr);

    // 8-9: zero user accumulators
    zero_f4<<<(nu4 + TB - 1) / TB, TB>>>(a1, nu4);
    zero_f4<<<(nu4 + TB - 1) / TB, TB>>>(a2, nu4);

    // 10: fused user-side scatter (t1 -> aggU1, t2 -> aggU2)
    scatter_user2<<<(E + 7) / 8, TB>>>(t1, t2, edge_src, edge_dst, a1, a2, E);

    // 11: zero movie accumulator
    zero_f4<<<(nm4 + TB - 1) / TB, TB>>>(aM, nm4);

    // 12: movie-side scatter of virtual user_h = relu(aggU1/deg + cU1)
    scatter_movie_uh<<<(E + 7) / 8, TB>>>(a1, edge_src, edge_dst, du, aM, E);

    // 13: user_o (in place over aggU2) = user_h @ Wr2_mu + bl2_mu + aggU2/deg
    //     user_h consumed virtually from aggU1 via A-side transform
    gemm_tc<<<gNU, TB>>>(a1, Wr2_mu, a2, nu, H, bl2_mu, nullptr, du, 2, du, cU1);

    // 14: movie_o (into g_mx) = (aggM/deg_m) @ Wl2_um + bl2_um ...
    gemm_tc<<<gNM, TB>>>(aM, Wl2_um, mx, nm, H, bl2_um, nullptr, dm, 3, nullptr, nullptr);
    // 15: ... += movie_h @ Wr2_um
    gemm_tc<<<gNM, TB>>>(mh, Wr2_um, mx, nm, H, nullptr, nullptr, nullptr, 4, nullptr, nullptr);

    // 16: supervision-edge dot products
    edge_dot<<<(EL + 7) / 8, TB>>>(a2, mx, lbl_user, lbl_movie, out, EL);
}